// round 12
// baseline (speedup 1.0000x reference)
#include <cuda_runtime.h>
#include <cuda_fp16.h>
#include <cstdint>

#define BATCH   128
#define INPUTS  65536
#define OUTPUTS 65536
#define TOPK    32

// Scratch (allocation-free rule: __device__ globals)
__device__ __half   g_xTh[(size_t)INPUTS * BATCH];   // 16 MB: x^T [input, batch], fp16
__device__ uint32_t g_pk[(size_t)OUTPUTS * TOPK];    // 8 MB: packed {idx:u16<<16 | w:f16}

// ---------------------------------------------------------------------------
// Kernel 1: transpose x [BATCH, INPUTS] -> g_xTh [INPUTS, BATCH] (fp16)
// 2 x (64x64) tiles per block -> 8 independent float4 loads in flight per
// thread before the sync (2x MLP vs round-10; kernel was latency-bound).
// Stores: warp per input-row, 32 x half2 = 128B contiguous.
// ---------------------------------------------------------------------------
__global__ __launch_bounds__(256) void k_transpose_x(const float* __restrict__ x) {
    __shared__ float tile[2][64][65];
    const int w  = threadIdx.x >> 5;
    const int l  = threadIdx.x & 31;
    const int b0 = blockIdx.y * 64;                // batch base
    const int iB = blockIdx.x * 128;               // input base (2 tiles)

    // load: 8 independent float4 loads per thread, then one sync
#pragma unroll
    for (int p = 0; p < 4; p++) {
        const int row = p * 16 + 2 * w + (l >> 4); // batch row in tile
        const int col = (l & 15) * 4;              // input col in tile
#pragma unroll
        for (int t = 0; t < 2; t++) {
            const float4 v = *reinterpret_cast<const float4*>(
                &x[(size_t)(b0 + row) * INPUTS + iB + t * 64 + col]);
            tile[t][row][col + 0] = v.x;
            tile[t][row][col + 1] = v.y;
            tile[t][row][col + 2] = v.z;
            tile[t][row][col + 3] = v.w;
        }
    }
    __syncthreads();

    // store: warp w -> input row q*8+w of each tile; lane l -> batches 2l,2l+1
#pragma unroll
    for (int t = 0; t < 2; t++) {
#pragma unroll
        for (int q = 0; q < 8; q++) {
            const int i  = q * 8 + w;
            const __half h0 = __float2half_rn(tile[t][2 * l][i]);
            const __half h1 = __float2half_rn(tile[t][2 * l + 1][i]);
            reinterpret_cast<__half2*>(
                &g_xTh[(size_t)(iB + t * 64 + i) * BATCH + b0])[l] =
                __halves2half2(h0, h1);
        }
    }
}

// ---------------------------------------------------------------------------
// Kernel 2: prep. Softmax over k per output column, pack {idx:u16, w:f16}
// into one u32 per (o,k). Dtype of top_indices self-detected per block.
// ---------------------------------------------------------------------------
__global__ __launch_bounds__(256) void k_prep(const float* __restrict__ tc,
                                              const void*  __restrict__ idx_raw) {
    __shared__ float    tct[32][33];
    __shared__ uint32_t ixt[32][33];
    __shared__ float    red[8][33];
    __shared__ float    cmax[32], cinv[32];

    const int tx = threadIdx.x, ty = threadIdx.y;
    const int tid = ty * 32 + tx;

    // self-detect idx dtype: int64 data has zero high words at odd i32 slots.
    // offsets 1..511 ints (2 KB) are in-bounds under both layouts.
    const int* idx32 = (const int*)idx_raw;
    const int  z     = (idx32[2 * tid + 1] == 0) ? 1 : 0;
    const int  is64  = __syncthreads_and(z);

    const long long* idx64 = (const long long*)idx_raw;
    const int o_in = blockIdx.x * 32 + tx;
#pragma unroll
    for (int i = 0; i < 32; i += 8) {
        const int k = ty + i;
        const size_t e = (size_t)k * OUTPUTS + o_in;
        tct[k][tx] = tc[e];
        ixt[k][tx] = (uint32_t)((is64 ? (int)idx64[e] : idx32[e]) & (INPUTS - 1));
    }
    __syncthreads();

    // softmax over k (column tx); this thread owns k = ty*4 .. ty*4+3
    float m = -1e30f;
#pragma unroll
    for (int j = 0; j < 4; j++) m = fmaxf(m, tct[ty * 4 + j][tx]);
    red[ty][tx] = m;
    __syncthreads();
    if (ty == 0) {
        float mm = red[0][tx];
#pragma unroll
        for (int r = 1; r < 8; r++) mm = fmaxf(mm, red[r][tx]);
        cmax[tx] = mm;
    }
    __syncthreads();
    const float cm = cmax[tx];
    float e4[4]; float s = 0.f;
#pragma unroll
    for (int j = 0; j < 4; j++) { e4[j] = __expf(tct[ty * 4 + j][tx] - cm); s += e4[j]; }
    red[ty][tx] = s;
    __syncthreads();
    if (ty == 0) {
        float ss = 0.f;
#pragma unroll
        for (int r = 0; r < 8; r++) ss += red[r][tx];
        cinv[tx] = 1.f / ss;
    }
    __syncthreads();
    const float inv = cinv[tx];
#pragma unroll
    for (int j = 0; j < 4; j++) {
        const int k = ty * 4 + j;
        const unsigned short h = __half_as_ushort(__float2half_rn(e4[j] * inv));
        ixt[k][tx] = (ixt[k][tx] << 16) | (uint32_t)h;   // own cell only, no race
    }
    __syncthreads();

    // coalesced write: g_pk[o][k], k contiguous across lanes
#pragma unroll
    for (int i = 0; i < 32; i += 8) {
        const int o_out = blockIdx.x * 32 + ty + i;
        g_pk[(size_t)o_out * TOPK + tx] = ixt[tx][ty + i];
    }
}

// ---------------------------------------------------------------------------
// Kernel 3: main. One warp per output column o; 2 k per iteration.
//   Lanes 0-15 gather row(2i), lanes 16-31 gather row(2i+1) via one LDG.128
//   (same 4 wavefronts as 2x LDG.64, half the LDG/SHFL/addr issue slots).
//   Lane (l16,hk) accumulates batches 8*l16..8*l16+7 for k parity hk;
//   epilogue shfl-xor(16) merges parities.
// ---------------------------------------------------------------------------
__global__ __launch_bounds__(256) void k_main(float* __restrict__ out) {
    __shared__ float sm[8][BATCH];            // [o_local][b]
    const int warp = threadIdx.x >> 5;
    const int lane = threadIdx.x & 31;
    const int l16  = lane & 15;
    const int hk   = lane >> 4;               // k parity handled by this lane
    const int o    = blockIdx.x * 8 + warp;

    const uint32_t pk = g_pk[(size_t)o * TOPK + lane];   // 128B/warp

    const char* __restrict__ xb = (const char*)g_xTh;
    float a0 = 0.f, a1 = 0.f, a2 = 0.f, a3 = 0.f;
    float a4 = 0.f, a5 = 0.f, a6 = 0.f, a7 = 0.f;
#pragma unroll
    for (int i = 0; i < TOPK / 2; i++) {
        const uint32_t p  = __shfl_sync(0xffffffffu, pk, 2 * i + hk);
        const float    wk = __low2float(*reinterpret_cast<const __half2*>(&p));
        const uint4    r  = *reinterpret_cast<const uint4*>(
                                xb + ((size_t)(p >> 16) << 8) + l16 * 16);
        const float2 f0 = __half22float2(*reinterpret_cast<const __half2*>(&r.x));
        const float2 f1 = __half22float2(*reinterpret_cast<const __half2*>(&r.y));
        const float2 f2 = __half22float2(*reinterpret_cast<const __half2*>(&r.z));
        const float2 f3 = __half22float2(*reinterpret_cast<const __half2*>(&r.w));
        a0 = fmaf(wk, f0.x, a0);  a1 = fmaf(wk, f0.y, a1);
        a2 = fmaf(wk, f1.x, a2);  a3 = fmaf(wk, f1.y, a3);
        a4 = fmaf(wk, f2.x, a4);  a5 = fmaf(wk, f2.y, a5);
        a6 = fmaf(wk, f3.x, a6);  a7 = fmaf(wk, f3.y, a7);
    }

    // merge the two k-parities: lanes l and l+16 hold the same batch set
    a0 += __shfl_xor_sync(0xffffffffu, a0, 16);
    a1 += __shfl_xor_sync(0xffffffffu, a1, 16);
    a2 += __shfl_xor_sync(0xffffffffu, a2, 16);
    a3 += __shfl_xor_sync(0xffffffffu, a3, 16);
    a4 += __shfl_xor_sync(0xffffffffu, a4, 16);
    a5 += __shfl_xor_sync(0xffffffffu, a5, 16);
    a6 += __shfl_xor_sync(0xffffffffu, a6, 16);
    a7 += __shfl_xor_sync(0xffffffffu, a7, 16);

    // stage: lane (l16,hk) writes float4 for batches 8*l16 + 4*hk .. +3
    float4* s4 = reinterpret_cast<float4*>(sm[warp]);
    s4[2 * l16 + hk] = hk ? make_float4(a4, a5, a6, a7)
                          : make_float4(a0, a1, a2, a3);
    __syncthreads();

    // write out: thread t -> b = t/2, 4 consecutive o starting at (t&1)*4
    const int t  = threadIdx.x;
    const int b  = t >> 1;
    const int j  = (t & 1) * 4;
    const int o0 = blockIdx.x * 8;
    const float4 v = make_float4(sm[j + 0][b], sm[j + 1][b], sm[j + 2][b], sm[j + 3][b]);
    *reinterpret_cast<float4*>(&out[(size_t)b * OUTPUTS + o0 + j]) = v;
}

// ---------------------------------------------------------------------------
extern "C" void kernel_launch(void* const* d_in, const int* in_sizes, int n_in,
                              void* d_out, int out_size) {
    const float* x   = (const float*)d_in[0];      // [128, 65536] f32
    const float* tc  = (const float*)d_in[1];      // [32, 65536]  f32
    const void*  idx = d_in[2];                    // [32, 65536]  i64 OR i32 (auto)
    float* out = (float*)d_out;                    // [128, 65536] f32

    dim3 tb(32, 8);
    k_transpose_x<<<dim3(INPUTS / 128, BATCH / 64), 256>>>(x);
    k_prep<<<OUTPUTS / 32, tb>>>(tc, idx);
    k_main<<<OUTPUTS / 8, 256>>>(out);
}

// round 15
// speedup vs baseline: 1.0328x; 1.0328x over previous
#include <cuda_runtime.h>
#include <cuda_fp16.h>
#include <cstdint>

#define BATCH   128
#define INPUTS  65536
#define OUTPUTS 65536
#define TOPK    32

// Scratch (allocation-free rule: __device__ globals)
__device__ __half   g_xTh[(size_t)INPUTS * BATCH];   // 16 MB: x^T [input, batch], fp16
__device__ uint32_t g_pk[(size_t)OUTPUTS * TOPK];    // 8 MB: packed {idx:u16<<16 | w:f16}

// ---------------------------------------------------------------------------
// Kernel 1: transpose x [BATCH, INPUTS] -> g_xTh [INPUTS, BATCH] (fp16)
// 64x64 tile (round-10 measured best: 11.7us). float4 gmem loads, scalar STS
// (65-float row stride is not 16B aligned), 128B half2 store rows.
// ---------------------------------------------------------------------------
__global__ __launch_bounds__(256) void k_transpose_x(const float* __restrict__ x) {
    __shared__ float tile[64][65];
    const int w  = threadIdx.x >> 5;
    const int l  = threadIdx.x & 31;
    const int i0 = blockIdx.x * 64;   // input-index base
    const int b0 = blockIdx.y * 64;   // batch base

#pragma unroll
    for (int p = 0; p < 4; p++) {
        const int row = p * 16 + 2 * w + (l >> 4);
        const int col = (l & 15) * 4;
        const float4 v = *reinterpret_cast<const float4*>(
            &x[(size_t)(b0 + row) * INPUTS + i0 + col]);
        tile[row][col + 0] = v.x;
        tile[row][col + 1] = v.y;
        tile[row][col + 2] = v.z;
        tile[row][col + 3] = v.w;
    }
    __syncthreads();

#pragma unroll
    for (int q = 0; q < 8; q++) {
        const int i  = q * 8 + w;
        const __half h0 = __float2half_rn(tile[2 * l][i]);
        const __half h1 = __float2half_rn(tile[2 * l + 1][i]);
        reinterpret_cast<__half2*>(&g_xTh[(size_t)(i0 + i) * BATCH + b0])[l] =
            __halves2half2(h0, h1);
    }
}

// ---------------------------------------------------------------------------
// Kernel 2: prep. Softmax over k per output column, pack {idx:u16, w:f16}
// into one u32 per (o,k). Dtype of top_indices self-detected per block.
// ---------------------------------------------------------------------------
__global__ __launch_bounds__(256) void k_prep(const float* __restrict__ tc,
                                              const void*  __restrict__ idx_raw) {
    __shared__ float    tct[32][33];
    __shared__ uint32_t ixt[32][33];
    __shared__ float    red[8][33];
    __shared__ float    cmax[32], cinv[32];

    const int tx = threadIdx.x, ty = threadIdx.y;
    const int tid = ty * 32 + tx;

    // self-detect idx dtype: int64 data has zero high words at odd i32 slots.
    // offsets 1..511 ints (2 KB) are in-bounds under both layouts.
    const int* idx32 = (const int*)idx_raw;
    const int  z     = (idx32[2 * tid + 1] == 0) ? 1 : 0;
    const int  is64  = __syncthreads_and(z);

    const long long* idx64 = (const long long*)idx_raw;
    const int o_in = blockIdx.x * 32 + tx;
#pragma unroll
    for (int i = 0; i < 32; i += 8) {
        const int k = ty + i;
        const size_t e = (size_t)k * OUTPUTS + o_in;
        tct[k][tx] = tc[e];
        ixt[k][tx] = (uint32_t)((is64 ? (int)idx64[e] : idx32[e]) & (INPUTS - 1));
    }
    __syncthreads();

    // softmax over k (column tx); this thread owns k = ty*4 .. ty*4+3
    float m = -1e30f;
#pragma unroll
    for (int j = 0; j < 4; j++) m = fmaxf(m, tct[ty * 4 + j][tx]);
    red[ty][tx] = m;
    __syncthreads();
    if (ty == 0) {
        float mm = red[0][tx];
#pragma unroll
        for (int r = 1; r < 8; r++) mm = fmaxf(mm, red[r][tx]);
        cmax[tx] = mm;
    }
    __syncthreads();
    const float cm = cmax[tx];
    float e4[4]; float s = 0.f;
#pragma unroll
    for (int j = 0; j < 4; j++) { e4[j] = __expf(tct[ty * 4 + j][tx] - cm); s += e4[j]; }
    red[ty][tx] = s;
    __syncthreads();
    if (ty == 0) {
        float ss = 0.f;
#pragma unroll
        for (int r = 0; r < 8; r++) ss += red[r][tx];
        cinv[tx] = 1.f / ss;
    }
    __syncthreads();
    const float inv = cinv[tx];
#pragma unroll
    for (int j = 0; j < 4; j++) {
        const int k = ty * 4 + j;
        const unsigned short h = __half_as_ushort(__float2half_rn(e4[j] * inv));
        ixt[k][tx] = (ixt[k][tx] << 16) | (uint32_t)h;   // own cell only, no race
    }
    __syncthreads();

    // coalesced write: g_pk[o][k], k contiguous across lanes
#pragma unroll
    for (int i = 0; i < 32; i += 8) {
        const int o_out = blockIdx.x * 32 + ty + i;
        g_pk[(size_t)o_out * TOPK + tx] = ixt[tx][ty + i];
    }
}

// ---------------------------------------------------------------------------
// Kernel 3: main. One warp per output column o. Per k: 1 SHFL (packed
// {idx,w}), 1 LDG.64.CG gather — .cg skips L1 allocation (zero-reuse random
// gathers; removes the L1 miss-fill pass that the round-3/8/12 data implies
// is the binding cost). Lane l owns batches 4l..4l+3.
// ---------------------------------------------------------------------------
__global__ __launch_bounds__(256) void k_main(float* __restrict__ out) {
    __shared__ float sm[8][BATCH];            // [o_local][b]
    const int warp = threadIdx.x >> 5;
    const int lane = threadIdx.x & 31;
    const int o    = blockIdx.x * 8 + warp;

    const uint32_t pk = g_pk[(size_t)o * TOPK + lane];   // 128B/warp

    const char* __restrict__ xb = (const char*)g_xTh;
    float a0 = 0.f, a1 = 0.f, a2 = 0.f, a3 = 0.f;
#pragma unroll
    for (int k = 0; k < TOPK; k++) {
        const uint32_t p  = __shfl_sync(0xffffffffu, pk, k);
        const float    wk = __low2float(*reinterpret_cast<const __half2*>(&p)); // w = low f16
        const uint2    r  = __ldcg(reinterpret_cast<const uint2*>(
                                xb + ((size_t)(p >> 16) << 8) + lane * 8));     // idx = high u16
        const float2 f01 = __half22float2(*reinterpret_cast<const __half2*>(&r.x));
        const float2 f23 = __half22float2(*reinterpret_cast<const __half2*>(&r.y));
        a0 = fmaf(wk, f01.x, a0);
        a1 = fmaf(wk, f01.y, a1);
        a2 = fmaf(wk, f23.x, a2);
        a3 = fmaf(wk, f23.y, a3);
    }

    // stage: lane l owns batches 4l..4l+3 of column o
    reinterpret_cast<float4*>(sm[warp])[lane] = make_float4(a0, a1, a2, a3);
    __syncthreads();

    // write out: thread t -> b = t/2, 4 consecutive o starting at (t&1)*4
    const int t  = threadIdx.x;
    const int b  = t >> 1;
    const int j  = (t & 1) * 4;
    const int o0 = blockIdx.x * 8;
    const float4 v = make_float4(sm[j + 0][b], sm[j + 1][b], sm[j + 2][b], sm[j + 3][b]);
    *reinterpret_cast<float4*>(&out[(size_t)b * OUTPUTS + o0 + j]) = v;
}

// ---------------------------------------------------------------------------
extern "C" void kernel_launch(void* const* d_in, const int* in_sizes, int n_in,
                              void* d_out, int out_size) {
    const float* x   = (const float*)d_in[0];      // [128, 65536] f32
    const float* tc  = (const float*)d_in[1];      // [32, 65536]  f32
    const void*  idx = d_in[2];                    // [32, 65536]  i64 OR i32 (auto)
    float* out = (float*)d_out;                    // [128, 65536] f32

    dim3 tb(32, 8);
    k_transpose_x<<<dim3(INPUTS / 64, BATCH / 64), 256>>>(x);
    k_prep<<<OUTPUTS / 32, tb>>>(tc, idx);
    k_main<<<OUTPUTS / 8, 256>>>(out);
}